// round 14
// baseline (speedup 1.0000x reference)
#include <cuda_runtime.h>
#include <cstddef>

// LoG = GaussianBlur(3,sigma=1) -> Laplacian(ksize=9) + 1, clip [0,255].
// Fused: composite 11x11 = A(x)B(y) + B(x)A(y), A = P9*[1,2,1], B = P9*[1,-2,1],
// P9 = gauss3 (*) binom6. Horizontal pass computes hP (9-tap) once, derives
// U = [1,2,1]*hP, W = [1,-2,1]*hP; vertical: out = cB*U + cA*W (+1, clip).
// 64x64 output tiles: band of 64 rows in 2 iterations of 32 with a 42-slot
// (U,W) ring; slot(row) = (row - band0 + 5) mod 42 == local r in both h-conv
// iterations (compile-time identity), v-conv wraps only in iteration 1.

#define Hn 512
#define Wn 512
#define ROWF 1536            // floats per image row (512*3)
#define TWP 64               // output pixels per block
#define BAND 64
#define IN_PITCH 76          // 74 px per row, 16B-aligned pitch
#define IN_PLANE 3192        // 42*76
#define HPP 130              // (U,W) float2 row pitch = 65 (odd -> good banks)
#define RNG 42               // ring slots (= live row window)
#define HAB_PLANE 5462       // 42*130=5460 +2; /2 = 2731 == 11 mod 16
#define NTHREADS 512

__device__ __forceinline__ int reflect101(int i, int n) {
    i = (i < 0) ? -i : i;
    return (i >= n) ? (2 * n - 2 - i) : i;
}

// ---- Phase 1: load NR rows (abs rows abs0..abs0+NR-1) into in_s rows 0.. ---
template<int NR>
__device__ __forceinline__ void load_rows(const float* __restrict__ xp,
                                          float* in_s, int p0, int abs0, int tid) {
    if (p0 != 0 && p0 != (Wn - TWP)) {
        // interior-W fast path: float4 loads, no column reflect math.
        // local float j (0..221) = input float 3*(p0-5)+j; base 3*p0-16 is
        // 16B-aligned; off = 4*col4 + l - 1.
        const int fidx0 = 3 * p0 - 16;
        const int col4  = tid & 63;                  // 0..63 (56..63 idle)
        int r = tid >> 6;                            // 0..7
        int qq[4], cc[4];
        bool val[4];
        #pragma unroll
        for (int l = 0; l < 4; l++) {
            int off = 4 * col4 + l - 1;
            val[l] = (off >= 0) && (off < 222);
            int o = val[l] ? off : 0;
            qq[l] = o / 3;
            cc[l] = o - 3 * qq[l];
        }
        const float4* gp = (const float4*)(xp + fidx0 + 4 * col4);
        #pragma unroll
        for (int k = 0; k < (NR + 7) / 8; k++) {
            if (r < NR && col4 < 56) {
                const int gh = reflect101(abs0 + r, Hn);
                float4 v = gp[gh * (ROWF / 4)];
                float vv[4] = {v.x, v.y, v.z, v.w};
                const int rb = r * IN_PITCH;
                #pragma unroll
                for (int l = 0; l < 4; l++)
                    if (val[l]) in_s[cc[l] * IN_PLANE + rb + qq[l]] = vv[l];
            }
            r += 8;
        }
    } else {
        // border-W scalar path (reflect both dims)
        const int f  = tid & 255;
        const int rg = tid >> 8;                     // 0..1
        if (f < 222) {
            const int q = f / 3;
            const int c = f - q * 3;
            const int wp = reflect101(p0 - 5 + q, Wn);
            const int src_col = wp * 3 + c;
            float* dst = in_s + c * IN_PLANE + q;
            #pragma unroll 2
            for (int r = rg; r < NR; r += 2) {
                const int gh = reflect101(abs0 + r, Hn);
                dst[r * IN_PITCH] = xp[(size_t)gh * ROWF + src_col];
            }
        }
    }
}

// ---- Phase 2: horizontal 9-tap hP -> (U,W); ring slot == local row r --------
// 3 ch * NR rows * 8 eight-output segments; grid-stride over 512 threads.
template<int NR>
__device__ __forceinline__ void hconv_rows(const float* in_s, float* hAB_s, int tid) {
    const float P9[9] = {
        0.2740686191f,  2.0962744762f,  7.0962744762f, 13.9037255238f,
        17.2593138094f, 13.9037255238f, 7.0962744762f,  2.0962744762f,
        0.2740686191f };

    #pragma unroll 1
    for (int task = tid; task < 3 * NR * 8; task += NTHREADS) {
        const int c   = task / (NR * 8);
        const int rem = task - c * (NR * 8);
        const int r   = rem >> 3;
        const int p   = (rem & 7) << 3;
        const float* src = in_s + c * IN_PLANE + r * IN_PITCH + p;

        float hP[10];
        #pragma unroll
        for (int m = 0; m < 10; m++) hP[m] = 0.f;

        #pragma unroll
        for (int ib = 0; ib < 4; ib++) {
            float4 v4 = *(const float4*)(src + 4 * ib);
            float vs[4] = {v4.x, v4.y, v4.z, v4.w};
            #pragma unroll
            for (int s = 0; s < 4; s++) {
                const int i = 4 * ib + s;
                const float v = vs[s];
                #pragma unroll
                for (int m = 0; m < 10; m++) {
                    const int t = i - m;
                    if (t >= 0 && t < 9) hP[m] = fmaf(P9[t], v, hP[m]);
                }
            }
        }
        {
            float2 v2 = *(const float2*)(src + 16);
            float vs[2] = {v2.x, v2.y};
            #pragma unroll
            for (int s = 0; s < 2; s++) {
                const int i = 16 + s;
                const float v = vs[s];
                #pragma unroll
                for (int m = 0; m < 10; m++) {
                    const int t = i - m;
                    if (t >= 0 && t < 9) hP[m] = fmaf(P9[t], v, hP[m]);
                }
            }
        }

        float2* d = (float2*)(hAB_s + c * HAB_PLANE + r * HPP) + p;
        #pragma unroll
        for (int j = 0; j < 8; j++) {
            const float s2 = hP[j] + hP[j + 2];
            d[j] = make_float2(fmaf(2.0f, hP[j + 1], s2),
                               fmaf(-2.0f, hP[j + 1], s2));
        }
    }
}

// ---- Phase 3: vertical 11-tap combine from ring, 16-row chunks --------------
// 192 columns (64 px * 3 ch) * 2 chunks = 384 tasks. OFF = 0: no wrap;
// OFF = 32: one conditional subtract + increment-wrap.
template<int OFF>
__device__ __forceinline__ void vconv_out(const float* hAB_s, float* __restrict__ out,
                                          size_t plane, int p0, int band0, int tid) {
    const float cA[11] = {
        0.274068619061f,  2.644411714f, 11.562892048f, 30.192548953f,
        52.163039333f,   62.326078667f, 52.163039333f, 30.192548953f,
        11.562892048f,    2.644411714f,  0.274068619061f };
    const float cB[11] = {
        0.274068619061f,  1.548137238f,  3.177794143f,  1.807451048f,
       -3.451862762f,    -6.711176571f, -3.451862762f,  1.807451048f,
        3.177794143f,     1.548137238f,  0.274068619061f };

    if (tid < 384) {
        const int col   = tid % 192;     // consecutive tid -> consecutive floats
        const int chunk = tid / 192;
        const int p = col / 3;
        const int c = col - p * 3;
        const int r0 = chunk * 16;
        const float2* bp = (const float2*)(hAB_s + c * HAB_PLANE) + p;

        float acc[16];
        #pragma unroll
        for (int j = 0; j < 16; j++) acc[j] = 1.0f;  // delta = 1

        if (OFF == 0) {
            #pragma unroll
            for (int i = 0; i < 26; i++) {
                const float2 v = bp[(r0 + i) * (HPP / 2)];
                #pragma unroll
                for (int j = 0; j < 16; j++) {
                    const int t = i - j;
                    if (t >= 0 && t < 11) {
                        acc[j] = fmaf(cB[t], v.x, acc[j]);
                        acc[j] = fmaf(cA[t], v.y, acc[j]);
                    }
                }
            }
        } else {
            int si = OFF + r0;
            if (si >= RNG) si -= RNG;
            #pragma unroll
            for (int i = 0; i < 26; i++) {
                const float2 v = bp[si * (HPP / 2)];
                si++;
                if (si == RNG) si = 0;
                #pragma unroll
                for (int j = 0; j < 16; j++) {
                    const int t = i - j;
                    if (t >= 0 && t < 11) {
                        acc[j] = fmaf(cB[t], v.x, acc[j]);
                        acc[j] = fmaf(cA[t], v.y, acc[j]);
                    }
                }
            }
        }
        float* op = out + plane + (size_t)(band0 + OFF + r0) * ROWF + p0 * 3 + col;
        #pragma unroll
        for (int j = 0; j < 16; j++)
            op[j * ROWF] = fminf(fmaxf(acc[j], 0.0f), 255.0f);
    }
}

__global__ __launch_bounds__(NTHREADS, 2)
void log_fused_kernel(const float* __restrict__ x, float* __restrict__ out) {
    extern __shared__ float smem[];
    float* in_s  = smem;                      // 3 planes [42][IN_PITCH]
    float* hAB_s = smem + 3 * IN_PLANE;       // 3 planes [RNG][HPP] (U,W) ring

    const int tid   = threadIdx.x;
    const int p0    = blockIdx.x * TWP;
    const int band0 = blockIdx.y * BAND;
    const size_t plane = (size_t)blockIdx.z * (size_t)(Hn * ROWF);
    const float* xp = x + plane;

    // --- iteration 0: full 42-row window, outputs band0..band0+31 ---
    load_rows<42>(xp, in_s, p0, band0 - 5, tid);
    __syncthreads();
    hconv_rows<42>(in_s, hAB_s, tid);
    __syncthreads();
    vconv_out<0>(hAB_s, out, plane, p0, band0, tid);

    // --- iteration 1: 32 new rows (slots 0..31), outputs band0+32..+63 ---
    load_rows<32>(xp, in_s, p0, band0 + 37, tid);
    __syncthreads();
    hconv_rows<32>(in_s, hAB_s, tid);
    __syncthreads();
    vconv_out<32>(hAB_s, out, plane, p0, band0, tid);
}

extern "C" void kernel_launch(void* const* d_in, const int* in_sizes, int n_in,
                              void* d_out, int out_size) {
    const float* x = (const float*)d_in[0];
    float* out = (float*)d_out;
    const int N = in_sizes[0] / (Hn * Wn * 3);

    const int smem_bytes = (3 * IN_PLANE + 3 * HAB_PLANE) * (int)sizeof(float);
    cudaFuncSetAttribute(log_fused_kernel,
                         cudaFuncAttributeMaxDynamicSharedMemorySize, smem_bytes);

    dim3 grid(Wn / TWP, Hn / BAND, N);   // (8, 8, N)
    log_fused_kernel<<<grid, NTHREADS, smem_bytes>>>(x, out);
}

// round 15
// speedup vs baseline: 1.3948x; 1.3948x over previous
#include <cuda_runtime.h>
#include <cstddef>

// LoG = GaussianBlur(3,sigma=1) -> Laplacian(ksize=9) + 1, clip [0,255].
// Fused: composite 11x11 = A(x)B(y) + B(x)A(y), A = P9*[1,2,1], B = P9*[1,-2,1],
// P9 = gauss3 (*) binom6. Horizontal pass computes hP (9-tap) once, derives
// U = [1,2,1]*hP, W = [1,-2,1]*hP; vertical: out = cB*U + cA*W (+1, clip).
// Banded: 64-row band in 2 iterations of 32 rows; 42-slot (U,W) ring with
// slot(row) = (row - band0 + 5) mod 42 == local r in both h-conv iterations.
// Phase 3 uses 384 threads (8-row chunks) for warp balance.

#define Hn 512
#define Wn 512
#define ROWF 1536            // floats per image row (512*3)
#define TWP 32
#define BAND 64
#define IN_PITCH 44          // 16B-aligned rows (deinterleaved channel planes)
#define IN_PLANE 1848        // 42*44
#define HPP 66               // (U,W) float2 row pitch = 33
#define RNG 42               // ring slots (= live row window)
#define HAB_PLANE 2774       // 42*66=2772 +2; /2 = 1387 == 11 mod 16
#define NTHREADS 512

__device__ __forceinline__ int reflect101(int i, int n) {
    i = (i < 0) ? -i : i;
    return (i >= n) ? (2 * n - 2 - i) : i;
}

// ---- Phase 1: load NR rows (abs rows abs0..abs0+NR-1) into in_s rows 0.. ---
template<int NR>
__device__ __forceinline__ void load_rows(const float* __restrict__ xp,
                                          float* in_s, int p0, int abs0, int tid) {
    if (p0 != 0 && p0 != (Wn - TWP)) {
        const int fidx0 = (p0 - 5) * 3 - 1;          // 16B-aligned start
        const int col4  = tid & 31;
        int r = tid >> 5;                            // 0..15
        int qq[4], cc[4];
        bool val[4];
        #pragma unroll
        for (int l = 0; l < 4; l++) {
            int off = 4 * col4 + l - 1;
            val[l] = (off >= 0) && (off < 126);
            int o = val[l] ? off : 0;
            qq[l] = o / 3;
            cc[l] = o - 3 * qq[l];
        }
        const float4* gp = (const float4*)(xp + fidx0 + 4 * col4);
        #pragma unroll
        for (int k = 0; k < (NR + 15) / 16; k++) {
            if (r < NR) {
                const int gh = reflect101(abs0 + r, Hn);
                float4 v = gp[gh * (ROWF / 4)];
                float vv[4] = {v.x, v.y, v.z, v.w};
                const int rb = r * IN_PITCH;
                #pragma unroll
                for (int l = 0; l < 4; l++)
                    if (val[l]) in_s[cc[l] * IN_PLANE + rb + qq[l]] = vv[l];
            }
            r += 16;
        }
    } else {
        const int f  = tid & 127;
        const int rg = tid >> 7;                     // 0..3
        if (f < 126) {
            const int q = f / 3;
            const int c = f - q * 3;
            const int wp = reflect101(p0 - 5 + q, Wn);
            const int src_col = wp * 3 + c;
            float* dst = in_s + c * IN_PLANE + q;
            #pragma unroll 4
            for (int r = rg; r < NR; r += 4) {
                const int gh = reflect101(abs0 + r, Hn);
                dst[r * IN_PITCH] = xp[(size_t)gh * ROWF + src_col];
            }
        }
    }
}

// ---- Phase 2: horizontal 9-tap hP -> (U,W); ring slot == local row r --------
template<int NR>
__device__ __forceinline__ void hconv_rows(const float* in_s, float* hAB_s, int tid) {
    const float P9[9] = {
        0.2740686191f,  2.0962744762f,  7.0962744762f, 13.9037255238f,
        17.2593138094f, 13.9037255238f, 7.0962744762f,  2.0962744762f,
        0.2740686191f };

    if (tid < 3 * NR * 4) {
        int c, rem;
        if (NR == 32) { c = tid >> 7; rem = tid & 127; }
        else          { c = tid / (NR * 4); rem = tid - c * (NR * 4); }
        const int r = rem >> 2;
        const int p = (rem & 3) << 3;
        const float* src = in_s + c * IN_PLANE + r * IN_PITCH + p;

        float hP[10];
        #pragma unroll
        for (int m = 0; m < 10; m++) hP[m] = 0.f;

        #pragma unroll
        for (int ib = 0; ib < 4; ib++) {
            float4 v4 = *(const float4*)(src + 4 * ib);
            float vs[4] = {v4.x, v4.y, v4.z, v4.w};
            #pragma unroll
            for (int s = 0; s < 4; s++) {
                const int i = 4 * ib + s;
                const float v = vs[s];
                #pragma unroll
                for (int m = 0; m < 10; m++) {
                    const int t = i - m;
                    if (t >= 0 && t < 9) hP[m] = fmaf(P9[t], v, hP[m]);
                }
            }
        }
        {
            float2 v2 = *(const float2*)(src + 16);
            float vs[2] = {v2.x, v2.y};
            #pragma unroll
            for (int s = 0; s < 2; s++) {
                const int i = 16 + s;
                const float v = vs[s];
                #pragma unroll
                for (int m = 0; m < 10; m++) {
                    const int t = i - m;
                    if (t >= 0 && t < 9) hP[m] = fmaf(P9[t], v, hP[m]);
                }
            }
        }

        // slot(row) = (row - band0 + 5) mod 42 == r for both iterations
        float2* d = (float2*)(hAB_s + c * HAB_PLANE + r * HPP) + p;
        #pragma unroll
        for (int j = 0; j < 8; j++) {
            const float s2 = hP[j] + hP[j + 2];
            d[j] = make_float2(fmaf(2.0f, hP[j + 1], s2),
                               fmaf(-2.0f, hP[j + 1], s2));
        }
    }
}

// ---- Phase 3: vertical 11-tap combine from ring, 8-row chunks ---------------
// 96 columns (32 px * 3 ch) * 4 chunks of 8 rows = 384 tasks (12 warps).
// OFF = 0: slots r0..r0+17, max 41 -> no wrap. OFF = 32: one conditional
// subtract at setup + increment-wrap.
template<int OFF>
__device__ __forceinline__ void vconv_out(const float* hAB_s, float* __restrict__ out,
                                          size_t plane, int p0, int band0, int tid) {
    const float cA[11] = {
        0.274068619061f,  2.644411714f, 11.562892048f, 30.192548953f,
        52.163039333f,   62.326078667f, 52.163039333f, 30.192548953f,
        11.562892048f,    2.644411714f,  0.274068619061f };
    const float cB[11] = {
        0.274068619061f,  1.548137238f,  3.177794143f,  1.807451048f,
       -3.451862762f,    -6.711176571f, -3.451862762f,  1.807451048f,
        3.177794143f,     1.548137238f,  0.274068619061f };

    if (tid < 384) {
        const int col   = tid % 96;      // consecutive tid -> consecutive floats
        const int chunk = tid / 96;      // 0..3
        const int p = col / 3;
        const int c = col - p * 3;
        const int r0 = chunk * 8;
        const float2* bp = (const float2*)(hAB_s + c * HAB_PLANE) + p;

        float acc[8];
        #pragma unroll
        for (int j = 0; j < 8; j++) acc[j] = 1.0f;   // delta = 1

        if (OFF == 0) {
            #pragma unroll
            for (int i = 0; i < 18; i++) {
                const float2 v = bp[(r0 + i) * (HPP / 2)];
                #pragma unroll
                for (int j = 0; j < 8; j++) {
                    const int t = i - j;
                    if (t >= 0 && t < 11) {
                        acc[j] = fmaf(cB[t], v.x, acc[j]);
                        acc[j] = fmaf(cA[t], v.y, acc[j]);
                    }
                }
            }
        } else {
            int si = OFF + r0;
            if (si >= RNG) si -= RNG;
            #pragma unroll
            for (int i = 0; i < 18; i++) {
                const float2 v = bp[si * (HPP / 2)];
                si++;
                if (si == RNG) si = 0;
                #pragma unroll
                for (int j = 0; j < 8; j++) {
                    const int t = i - j;
                    if (t >= 0 && t < 11) {
                        acc[j] = fmaf(cB[t], v.x, acc[j]);
                        acc[j] = fmaf(cA[t], v.y, acc[j]);
                    }
                }
            }
        }
        float* op = out + plane + (size_t)(band0 + OFF + r0) * ROWF + p0 * 3 + col;
        #pragma unroll
        for (int j = 0; j < 8; j++)
            op[j * ROWF] = fminf(fmaxf(acc[j], 0.0f), 255.0f);
    }
}

__global__ __launch_bounds__(NTHREADS, 4)
void log_fused_kernel(const float* __restrict__ x, float* __restrict__ out) {
    extern __shared__ float smem[];
    float* in_s  = smem;                      // 3 planes [42][IN_PITCH]
    float* hAB_s = smem + 3 * IN_PLANE;       // 3 planes [RNG][HPP] (U,W) ring

    const int tid   = threadIdx.x;
    const int p0    = blockIdx.x * TWP;
    const int band0 = blockIdx.y * BAND;
    const size_t plane = (size_t)blockIdx.z * (size_t)(Hn * ROWF);
    const float* xp = x + plane;

    // --- iteration 0: full 42-row window, outputs band0..band0+31 ---
    load_rows<42>(xp, in_s, p0, band0 - 5, tid);
    __syncthreads();
    hconv_rows<42>(in_s, hAB_s, tid);
    __syncthreads();
    vconv_out<0>(hAB_s, out, plane, p0, band0, tid);

    // --- iteration 1: 32 new rows (slots 0..31), outputs band0+32..+63 ---
    // load overlaps trailing vconv warps (disjoint buffers); the sync after
    // load orders vconv's ring reads before hconv's ring writes.
    load_rows<32>(xp, in_s, p0, band0 + 37, tid);
    __syncthreads();
    hconv_rows<32>(in_s, hAB_s, tid);
    __syncthreads();
    vconv_out<32>(hAB_s, out, plane, p0, band0, tid);
}

extern "C" void kernel_launch(void* const* d_in, const int* in_sizes, int n_in,
                              void* d_out, int out_size) {
    const float* x = (const float*)d_in[0];
    float* out = (float*)d_out;
    const int N = in_sizes[0] / (Hn * Wn * 3);

    const int smem_bytes = (3 * IN_PLANE + 3 * HAB_PLANE) * (int)sizeof(float);
    cudaFuncSetAttribute(log_fused_kernel,
                         cudaFuncAttributeMaxDynamicSharedMemorySize, smem_bytes);

    dim3 grid(Wn / TWP, Hn / BAND, N);   // (16, 8, N)
    log_fused_kernel<<<grid, NTHREADS, smem_bytes>>>(x, out);
}

// round 16
// speedup vs baseline: 1.5093x; 1.0821x over previous
#include <cuda_runtime.h>
#include <cstddef>

// LoG = GaussianBlur(3,sigma=1) -> Laplacian(ksize=9) + 1, clip [0,255].
// Fused: composite 11x11 = A(x)B(y) + B(x)A(y), A = P9*[1,2,1], B = P9*[1,-2,1],
// P9 = gauss3 (*) binom6. Horizontal pass computes hP (9-tap) once, derives
// U = [1,2,1]*hP, W = [1,-2,1]*hP; vertical: out = cB*U + cA*W (+1, clip).
// Banded: 64-row band in 2 iterations of 32 rows; 42-slot (U,W) ring with
// slot(row) = (row - band0 + 5) mod 42 == local r in both h-conv iterations.
// Phase-3 iteration 1 is specialized per chunk into straight-line segments
// with compile-time slot offsets (no runtime wrap arithmetic).

#define Hn 512
#define Wn 512
#define ROWF 1536            // floats per image row (512*3)
#define TWP 32
#define BAND 64
#define IN_PITCH 44          // 16B-aligned rows (deinterleaved channel planes)
#define IN_PLANE 1848        // 42*44
#define HPP 66               // (U,W) float2 row pitch = 33
#define RNG 42               // ring slots (= live row window)
#define HAB_PLANE 2774       // 42*66=2772 +2; /2 = 1387 == 11 mod 16
#define NTHREADS 512

__device__ __forceinline__ int reflect101(int i, int n) {
    i = (i < 0) ? -i : i;
    return (i >= n) ? (2 * n - 2 - i) : i;
}

// ---- Phase 1: load NR rows (abs rows abs0..abs0+NR-1) into in_s rows 0.. ---
template<int NR>
__device__ __forceinline__ void load_rows(const float* __restrict__ xp,
                                          float* in_s, int p0, int abs0, int tid) {
    if (p0 != 0 && p0 != (Wn - TWP)) {
        const int fidx0 = (p0 - 5) * 3 - 1;          // 16B-aligned start
        const int col4  = tid & 31;
        int r = tid >> 5;                            // 0..15
        int qq[4], cc[4];
        bool val[4];
        #pragma unroll
        for (int l = 0; l < 4; l++) {
            int off = 4 * col4 + l - 1;
            val[l] = (off >= 0) && (off < 126);
            int o = val[l] ? off : 0;
            qq[l] = o / 3;
            cc[l] = o - 3 * qq[l];
        }
        const float4* gp = (const float4*)(xp + fidx0 + 4 * col4);
        #pragma unroll
        for (int k = 0; k < (NR + 15) / 16; k++) {
            if (r < NR) {
                const int gh = reflect101(abs0 + r, Hn);
                float4 v = gp[gh * (ROWF / 4)];
                float vv[4] = {v.x, v.y, v.z, v.w};
                const int rb = r * IN_PITCH;
                #pragma unroll
                for (int l = 0; l < 4; l++)
                    if (val[l]) in_s[cc[l] * IN_PLANE + rb + qq[l]] = vv[l];
            }
            r += 16;
        }
    } else {
        const int f  = tid & 127;
        const int rg = tid >> 7;                     // 0..3
        if (f < 126) {
            const int q = f / 3;
            const int c = f - q * 3;
            const int wp = reflect101(p0 - 5 + q, Wn);
            const int src_col = wp * 3 + c;
            float* dst = in_s + c * IN_PLANE + q;
            #pragma unroll 4
            for (int r = rg; r < NR; r += 4) {
                const int gh = reflect101(abs0 + r, Hn);
                dst[r * IN_PITCH] = xp[(size_t)gh * ROWF + src_col];
            }
        }
    }
}

// ---- Phase 2: horizontal 9-tap hP -> (U,W); ring slot == local row r --------
template<int NR>
__device__ __forceinline__ void hconv_rows(const float* in_s, float* hAB_s, int tid) {
    const float P9[9] = {
        0.2740686191f,  2.0962744762f,  7.0962744762f, 13.9037255238f,
        17.2593138094f, 13.9037255238f, 7.0962744762f,  2.0962744762f,
        0.2740686191f };

    if (tid < 3 * NR * 4) {
        int c, rem;
        if (NR == 32) { c = tid >> 7; rem = tid & 127; }
        else          { c = tid / (NR * 4); rem = tid - c * (NR * 4); }
        const int r = rem >> 2;
        const int p = (rem & 3) << 3;
        const float* src = in_s + c * IN_PLANE + r * IN_PITCH + p;

        float hP[10];
        #pragma unroll
        for (int m = 0; m < 10; m++) hP[m] = 0.f;

        #pragma unroll
        for (int ib = 0; ib < 4; ib++) {
            float4 v4 = *(const float4*)(src + 4 * ib);
            float vs[4] = {v4.x, v4.y, v4.z, v4.w};
            #pragma unroll
            for (int s = 0; s < 4; s++) {
                const int i = 4 * ib + s;
                const float v = vs[s];
                #pragma unroll
                for (int m = 0; m < 10; m++) {
                    const int t = i - m;
                    if (t >= 0 && t < 9) hP[m] = fmaf(P9[t], v, hP[m]);
                }
            }
        }
        {
            float2 v2 = *(const float2*)(src + 16);
            float vs[2] = {v2.x, v2.y};
            #pragma unroll
            for (int s = 0; s < 2; s++) {
                const int i = 16 + s;
                const float v = vs[s];
                #pragma unroll
                for (int m = 0; m < 10; m++) {
                    const int t = i - m;
                    if (t >= 0 && t < 9) hP[m] = fmaf(P9[t], v, hP[m]);
                }
            }
        }

        // slot(row) = (row - band0 + 5) mod 42 == r for both iterations
        float2* d = (float2*)(hAB_s + c * HAB_PLANE + r * HPP) + p;
        #pragma unroll
        for (int j = 0; j < 8; j++) {
            const float s2 = hP[j] + hP[j + 2];
            d[j] = make_float2(fmaf(2.0f, hP[j + 1], s2),
                               fmaf(-2.0f, hP[j + 1], s2));
        }
    }
}

// ---- shared accumulate helper: one ring row i into the 16 accumulators -----
__device__ __forceinline__ void acc_row(float* acc, const float2 v, const int i,
                                        const float* cA, const float* cB) {
    #pragma unroll
    for (int j = 0; j < 16; j++) {
        const int t = i - j;
        if (t >= 0 && t < 11) {
            acc[j] = fmaf(cB[t], v.x, acc[j]);
            acc[j] = fmaf(cA[t], v.y, acc[j]);
        }
    }
}

// ---- Phase 3: vertical 11-tap combine from ring, 16-row chunks --------------
// 96 columns (32 px * 3 ch) * 2 chunks = 192 tasks. OFF = 0: slots r0..r0+25
// (no wrap). OFF = 32: chunk0 reads slots 32..41,0..15; chunk1 reads 6..31 —
// both straight-line with constant offsets (chunk is warp-uniform).
template<int OFF>
__device__ __forceinline__ void vconv_out(const float* hAB_s, float* __restrict__ out,
                                          size_t plane, int p0, int band0, int tid) {
    const float cA[11] = {
        0.274068619061f,  2.644411714f, 11.562892048f, 30.192548953f,
        52.163039333f,   62.326078667f, 52.163039333f, 30.192548953f,
        11.562892048f,    2.644411714f,  0.274068619061f };
    const float cB[11] = {
        0.274068619061f,  1.548137238f,  3.177794143f,  1.807451048f,
       -3.451862762f,    -6.711176571f, -3.451862762f,  1.807451048f,
        3.177794143f,     1.548137238f,  0.274068619061f };

    if (tid < 192) {
        const int col   = tid % 96;      // consecutive tid -> consecutive floats
        const int chunk = tid / 96;      // 0 or 1 (warp-uniform)
        const int p = col / 3;
        const int c = col - p * 3;
        const int r0 = chunk * 16;
        const float2* bp = (const float2*)(hAB_s + c * HAB_PLANE) + p;

        float acc[16];
        #pragma unroll
        for (int j = 0; j < 16; j++) acc[j] = 1.0f;  // delta = 1

        if (OFF == 0) {
            #pragma unroll
            for (int i = 0; i < 26; i++)
                acc_row(acc, bp[(r0 + i) * (HPP / 2)], i, cA, cB);
        } else {
            if (chunk == 0) {
                // slots 32..41 (i = 0..9), then 0..15 (i = 10..25)
                #pragma unroll
                for (int i = 0; i < 10; i++)
                    acc_row(acc, bp[(32 + i) * (HPP / 2)], i, cA, cB);
                #pragma unroll
                for (int i = 10; i < 26; i++)
                    acc_row(acc, bp[(i - 10) * (HPP / 2)], i, cA, cB);
            } else {
                // slots 6..31 (i = 0..25), no wrap
                #pragma unroll
                for (int i = 0; i < 26; i++)
                    acc_row(acc, bp[(6 + i) * (HPP / 2)], i, cA, cB);
            }
        }
        float* op = out + plane + (size_t)(band0 + OFF + r0) * ROWF + p0 * 3 + col;
        #pragma unroll
        for (int j = 0; j < 16; j++)
            op[j * ROWF] = fminf(fmaxf(acc[j], 0.0f), 255.0f);
    }
}

__global__ __launch_bounds__(NTHREADS, 4)
void log_fused_kernel(const float* __restrict__ x, float* __restrict__ out) {
    extern __shared__ float smem[];
    float* in_s  = smem;                      // 3 planes [42][IN_PITCH]
    float* hAB_s = smem + 3 * IN_PLANE;       // 3 planes [RNG][HPP] (U,W) ring

    const int tid   = threadIdx.x;
    const int p0    = blockIdx.x * TWP;
    const int band0 = blockIdx.y * BAND;
    const size_t plane = (size_t)blockIdx.z * (size_t)(Hn * ROWF);
    const float* xp = x + plane;

    // --- iteration 0: full 42-row window, outputs band0..band0+31 ---
    load_rows<42>(xp, in_s, p0, band0 - 5, tid);
    __syncthreads();
    hconv_rows<42>(in_s, hAB_s, tid);
    __syncthreads();
    vconv_out<0>(hAB_s, out, plane, p0, band0, tid);

    // --- iteration 1: 32 new rows (slots 0..31), outputs band0+32..+63 ---
    // load overlaps trailing vconv warps (disjoint buffers); the sync after
    // load orders vconv's ring reads before hconv's ring writes.
    load_rows<32>(xp, in_s, p0, band0 + 37, tid);
    __syncthreads();
    hconv_rows<32>(in_s, hAB_s, tid);
    __syncthreads();
    vconv_out<32>(hAB_s, out, plane, p0, band0, tid);
}

extern "C" void kernel_launch(void* const* d_in, const int* in_sizes, int n_in,
                              void* d_out, int out_size) {
    const float* x = (const float*)d_in[0];
    float* out = (float*)d_out;
    const int N = in_sizes[0] / (Hn * Wn * 3);

    const int smem_bytes = (3 * IN_PLANE + 3 * HAB_PLANE) * (int)sizeof(float);
    cudaFuncSetAttribute(log_fused_kernel,
                         cudaFuncAttributeMaxDynamicSharedMemorySize, smem_bytes);

    dim3 grid(Wn / TWP, Hn / BAND, N);   // (16, 8, N)
    log_fused_kernel<<<grid, NTHREADS, smem_bytes>>>(x, out);
}

// round 17
// speedup vs baseline: 1.5181x; 1.0058x over previous
#include <cuda_runtime.h>
#include <cstddef>

// LoG = GaussianBlur(3,sigma=1) -> Laplacian(ksize=9) + 1, clip [0,255].
// Fully factored: A = P9*[1,2,1], B = P9*[1,-2,1], P9 = gauss3 (*) binom6.
// Horizontal: hP (9-tap P9) -> U = [1,2,1]*hP, W = [1,-2,1]*hP.
// Vertical:   out = cB*U + cA*W + 1 = P9_y (*) Z + 1,
//             Z(m) = U(m-1)-2U(m)+U(m+1) + W(m-1)+2W(m)+W(m+1).
// Banded: 64-row band in 2 iterations of 32 rows; 42-slot (U,W) ring with
// slot(row) = (row - band0 + 5) mod 42 == local r in both h-conv iterations;
// phase-3 slot sequences are straight-line compile-time segments.

#define Hn 512
#define Wn 512
#define ROWF 1536            // floats per image row (512*3)
#define TWP 32
#define BAND 64
#define IN_PITCH 44          // 16B-aligned rows (deinterleaved channel planes)
#define IN_PLANE 1848        // 42*44
#define HPP 66               // (U,W) float2 row pitch = 33
#define RNG 42               // ring slots (= live row window)
#define HAB_PLANE 2774       // 42*66=2772 +2; /2 = 1387 == 11 mod 16
#define NTHREADS 512

__device__ __forceinline__ int reflect101(int i, int n) {
    i = (i < 0) ? -i : i;
    return (i >= n) ? (2 * n - 2 - i) : i;
}

// ---- Phase 1: load NR rows (abs rows abs0..abs0+NR-1) into in_s rows 0.. ---
template<int NR>
__device__ __forceinline__ void load_rows(const float* __restrict__ xp,
                                          float* in_s, int p0, int abs0, int tid) {
    if (p0 != 0 && p0 != (Wn - TWP)) {
        const int fidx0 = (p0 - 5) * 3 - 1;          // 16B-aligned start
        const int col4  = tid & 31;
        int r = tid >> 5;                            // 0..15
        int qq[4], cc[4];
        bool val[4];
        #pragma unroll
        for (int l = 0; l < 4; l++) {
            int off = 4 * col4 + l - 1;
            val[l] = (off >= 0) && (off < 126);
            int o = val[l] ? off : 0;
            qq[l] = o / 3;
            cc[l] = o - 3 * qq[l];
        }
        const float4* gp = (const float4*)(xp + fidx0 + 4 * col4);
        #pragma unroll
        for (int k = 0; k < (NR + 15) / 16; k++) {
            if (r < NR) {
                const int gh = reflect101(abs0 + r, Hn);
                float4 v = gp[gh * (ROWF / 4)];
                float vv[4] = {v.x, v.y, v.z, v.w};
                const int rb = r * IN_PITCH;
                #pragma unroll
                for (int l = 0; l < 4; l++)
                    if (val[l]) in_s[cc[l] * IN_PLANE + rb + qq[l]] = vv[l];
            }
            r += 16;
        }
    } else {
        const int f  = tid & 127;
        const int rg = tid >> 7;                     // 0..3
        if (f < 126) {
            const int q = f / 3;
            const int c = f - q * 3;
            const int wp = reflect101(p0 - 5 + q, Wn);
            const int src_col = wp * 3 + c;
            float* dst = in_s + c * IN_PLANE + q;
            #pragma unroll 4
            for (int r = rg; r < NR; r += 4) {
                const int gh = reflect101(abs0 + r, Hn);
                dst[r * IN_PITCH] = xp[(size_t)gh * ROWF + src_col];
            }
        }
    }
}

// ---- Phase 2: horizontal 9-tap hP -> (U,W); ring slot == local row r --------
template<int NR>
__device__ __forceinline__ void hconv_rows(const float* in_s, float* hAB_s, int tid) {
    const float P9[9] = {
        0.2740686191f,  2.0962744762f,  7.0962744762f, 13.9037255238f,
        17.2593138094f, 13.9037255238f, 7.0962744762f,  2.0962744762f,
        0.2740686191f };

    if (tid < 3 * NR * 4) {
        int c, rem;
        if (NR == 32) { c = tid >> 7; rem = tid & 127; }
        else          { c = tid / (NR * 4); rem = tid - c * (NR * 4); }
        const int r = rem >> 2;
        const int p = (rem & 3) << 3;
        const float* src = in_s + c * IN_PLANE + r * IN_PITCH + p;

        float hP[10];
        #pragma unroll
        for (int m = 0; m < 10; m++) hP[m] = 0.f;

        #pragma unroll
        for (int ib = 0; ib < 4; ib++) {
            float4 v4 = *(const float4*)(src + 4 * ib);
            float vs[4] = {v4.x, v4.y, v4.z, v4.w};
            #pragma unroll
            for (int s = 0; s < 4; s++) {
                const int i = 4 * ib + s;
                const float v = vs[s];
                #pragma unroll
                for (int m = 0; m < 10; m++) {
                    const int t = i - m;
                    if (t >= 0 && t < 9) hP[m] = fmaf(P9[t], v, hP[m]);
                }
            }
        }
        {
            float2 v2 = *(const float2*)(src + 16);
            float vs[2] = {v2.x, v2.y};
            #pragma unroll
            for (int s = 0; s < 2; s++) {
                const int i = 16 + s;
                const float v = vs[s];
                #pragma unroll
                for (int m = 0; m < 10; m++) {
                    const int t = i - m;
                    if (t >= 0 && t < 9) hP[m] = fmaf(P9[t], v, hP[m]);
                }
            }
        }

        // slot(row) = (row - band0 + 5) mod 42 == r for both iterations
        float2* d = (float2*)(hAB_s + c * HAB_PLANE + r * HPP) + p;
        #pragma unroll
        for (int j = 0; j < 8; j++) {
            const float s2 = hP[j] + hP[j + 2];
            d[j] = make_float2(fmaf(2.0f, hP[j + 1], s2),
                               fmaf(-2.0f, hP[j + 1], s2));
        }
    }
}

// ---- vertical streaming core: 26 window rows -> 16 outputs via P9 (*) Z ----
// SPLIT=false: rows at bp[i*33], i = 0..25.
// SPLIT=true:  rows at slots 32..41 (i<10) then i-10 (i>=10) of bp.
template<bool SPLIT>
__device__ __forceinline__ void vcore(const float2* bp, float* acc,
                                      const float* P9v) {
    auto ld = [&](int i) -> float2 {
        const int slot = SPLIT ? ((i < 10) ? (32 + i) : (i - 10)) : i;
        return bp[slot * (HPP / 2)];
    };
    float2 v0 = ld(0);
    float2 v1 = ld(1);
    #pragma unroll
    for (int i = 2; i < 26; i++) {
        const float2 v2 = ld(i);
        const int m = i - 1;
        float z = (v0.x + v2.x) + (v0.y + v2.y);
        z = fmaf(-2.0f, v1.x, z);
        z = fmaf( 2.0f, v1.y, z);
        #pragma unroll
        for (int j = 0; j < 16; j++) {
            const int t = m - 1 - j;
            if (t >= 0 && t < 9)
                acc[j] = fmaf(P9v[t], z, acc[j]);
        }
        v0 = v1;
        v1 = v2;
    }
}

// ---- Phase 3: vertical combine from ring, 16-row chunks ---------------------
// 96 columns (32 px * 3 ch) * 2 chunks = 192 tasks. OFF = 0: slots r0..r0+25
// (no wrap). OFF = 32: chunk0 slots 32..41,0..15 (SPLIT); chunk1 slots 6..31.
template<int OFF>
__device__ __forceinline__ void vconv_out(const float* hAB_s, float* __restrict__ out,
                                          size_t plane, int p0, int band0, int tid) {
    const float P9v[9] = {
        0.2740686191f,  2.0962744762f,  7.0962744762f, 13.9037255238f,
        17.2593138094f, 13.9037255238f, 7.0962744762f,  2.0962744762f,
        0.2740686191f };

    if (tid < 192) {
        const int col   = tid % 96;      // consecutive tid -> consecutive floats
        const int chunk = tid / 96;      // 0 or 1 (warp-uniform)
        const int p = col / 3;
        const int c = col - p * 3;
        const int r0 = chunk * 16;
        const float2* bp = (const float2*)(hAB_s + c * HAB_PLANE) + p;

        float acc[16];
        #pragma unroll
        for (int j = 0; j < 16; j++) acc[j] = 1.0f;  // delta = 1

        if (OFF == 0) {
            vcore<false>(bp + r0 * (HPP / 2), acc, P9v);
        } else if (chunk == 0) {
            vcore<true>(bp, acc, P9v);
        } else {
            vcore<false>(bp + 6 * (HPP / 2), acc, P9v);
        }

        float* op = out + plane + (size_t)(band0 + OFF + r0) * ROWF + p0 * 3 + col;
        #pragma unroll
        for (int j = 0; j < 16; j++)
            op[j * ROWF] = fminf(fmaxf(acc[j], 0.0f), 255.0f);
    }
}

__global__ __launch_bounds__(NTHREADS, 4)
void log_fused_kernel(const float* __restrict__ x, float* __restrict__ out) {
    extern __shared__ float smem[];
    float* in_s  = smem;                      // 3 planes [42][IN_PITCH]
    float* hAB_s = smem + 3 * IN_PLANE;       // 3 planes [RNG][HPP] (U,W) ring

    const int tid   = threadIdx.x;
    const int p0    = blockIdx.x * TWP;
    const int band0 = blockIdx.y * BAND;
    const size_t plane = (size_t)blockIdx.z * (size_t)(Hn * ROWF);
    const float* xp = x + plane;

    // --- iteration 0: full 42-row window, outputs band0..band0+31 ---
    load_rows<42>(xp, in_s, p0, band0 - 5, tid);
    __syncthreads();
    hconv_rows<42>(in_s, hAB_s, tid);
    __syncthreads();
    vconv_out<0>(hAB_s, out, plane, p0, band0, tid);

    // --- iteration 1: 32 new rows (slots 0..31), outputs band0+32..+63 ---
    // load overlaps trailing vconv warps (disjoint buffers); the sync after
    // load orders vconv's ring reads before hconv's ring writes.
    load_rows<32>(xp, in_s, p0, band0 + 37, tid);
    __syncthreads();
    hconv_rows<32>(in_s, hAB_s, tid);
    __syncthreads();
    vconv_out<32>(hAB_s, out, plane, p0, band0, tid);
}

extern "C" void kernel_launch(void* const* d_in, const int* in_sizes, int n_in,
                              void* d_out, int out_size) {
    const float* x = (const float*)d_in[0];
    float* out = (float*)d_out;
    const int N = in_sizes[0] / (Hn * Wn * 3);

    const int smem_bytes = (3 * IN_PLANE + 3 * HAB_PLANE) * (int)sizeof(float);
    cudaFuncSetAttribute(log_fused_kernel,
                         cudaFuncAttributeMaxDynamicSharedMemorySize, smem_bytes);

    dim3 grid(Wn / TWP, Hn / BAND, N);   // (16, 8, N)
    log_fused_kernel<<<grid, NTHREADS, smem_bytes>>>(x, out);
}